// round 1
// baseline (speedup 1.0000x reference)
#include <cuda_runtime.h>
#include <cstdint>

#define B_SZ 16384
#define IN_DIM 784
#define HID 400
#define OUT_DIM 10
#define T_STEPS 20
#define NWORDS 25   // ceil(784/32), bits 784..799 padded to zero

// -------- scratch state (static device allocations; allowed) --------
__device__ uint32_t g_xi[T_STEPS * NWORDS * B_SZ];   // spike bitmasks [t][w][m]  (~33 MB)
__device__ float    g_h1mem[B_SZ * HID];             // LIF1 membrane (~26 MB)
__device__ float    g_h2mem[B_SZ * OUT_DIM];         // LIF2 membrane

struct KeyArr { unsigned int a[T_STEPS]; unsigned int b[T_STEPS]; };

// -------- threefry2x32 (exact JAX semantics, 20 rounds) --------
__host__ __device__ __forceinline__ void tf_round(unsigned &x0, unsigned &x1, int r){
  x0 += x1;
#ifdef __CUDA_ARCH__
  x1 = __funnelshift_l(x1, x1, r);   // rotate-left
#else
  x1 = (x1 << r) | (x1 >> (32 - r));
#endif
  x1 ^= x0;
}

__host__ __device__ __forceinline__ void threefry2x32(unsigned k0, unsigned k1,
                                                      unsigned x0, unsigned x1,
                                                      unsigned &o0, unsigned &o1){
  unsigned k2 = k0 ^ k1 ^ 0x1BD11BDAu;
  x0 += k0; x1 += k1;
  tf_round(x0,x1,13); tf_round(x0,x1,15); tf_round(x0,x1,26); tf_round(x0,x1, 6);
  x0 += k1; x1 += k2 + 1u;
  tf_round(x0,x1,17); tf_round(x0,x1,29); tf_round(x0,x1,16); tf_round(x0,x1,24);
  x0 += k2; x1 += k0 + 2u;
  tf_round(x0,x1,13); tf_round(x0,x1,15); tf_round(x0,x1,26); tf_round(x0,x1, 6);
  x0 += k0; x1 += k1 + 3u;
  tf_round(x0,x1,17); tf_round(x0,x1,29); tf_round(x0,x1,16); tf_round(x0,x1,24);
  x0 += k1; x1 += k2 + 4u;
  tf_round(x0,x1,13); tf_round(x0,x1,15); tf_round(x0,x1,26); tf_round(x0,x1, 6);
  x0 += k2; x1 += k0 + 5u;
  o0 = x0; o1 = x1;
}

// -------- init: zero all state + output accumulator --------
__global__ void init_state(float* __restrict__ out){
  int i = blockIdx.x * 256 + threadIdx.x;            // grid sized to exactly B*HID
  if (i < B_SZ * HID)   g_h1mem[i] = 0.0f;
  if (i < B_SZ * OUT_DIM){ g_h2mem[i] = 0.0f; out[i] = 0.0f; }
}

// -------- spike generation: all T steps, packed bitmasks --------
// partitionable threefry: bits(i) = o0^o1 of threefry(key_t, (0, i)), i = m*784+k
// u = bitcast((bits>>9)|0x3f800000) - 1 ; spike = x > u  (strict)
__global__ __launch_bounds__(256) void spikegen(const float* __restrict__ x, KeyArr keys){
  int w    = blockIdx.x;                       // word index 0..24
  int t    = blockIdx.z;                       // timestep
  int m    = blockIdx.y * 8 + (threadIdx.x >> 5);
  int lane = threadIdx.x & 31;
  int k    = w * 32 + lane;

  unsigned k1 = keys.a[t], k2 = keys.b[t];
  unsigned i  = (unsigned)m * IN_DIM + (unsigned)k;

  unsigned o0, o1;
  threefry2x32(k1, k2, 0u, i, o0, o1);
  unsigned bits = o0 ^ o1;
  float u = __uint_as_float((bits >> 9) | 0x3f800000u) - 1.0f;

  bool s = false;
  if (k < IN_DIM) s = (x[i] > u);
  unsigned word = __ballot_sync(0xffffffffu, s);
  if (lane == 0) g_xi[(t * NWORDS + w) * B_SZ + m] = word;
}

// -------- GEMM1 (xi @ W1^T) fused with LIF layer 1 --------
// block: 64 rows x 40 hidden cols, 160 threads, thread tile 4x4, BK=32 (one bit-word)
__global__ __launch_bounds__(160) void gemm1_lif(const float* __restrict__ W1,
                                                 const float* __restrict__ b1, int t){
  __shared__ float As[32][64];
  __shared__ float Ws[32][40];
  int tid = threadIdx.x;
  int bm0 = blockIdx.x * 64;
  int n0  = blockIdx.y * 40;
  int tn  = tid % 10;
  int tm  = tid / 10;   // 0..15
  float c[4][4] = {};

  for (int kt = 0; kt < NWORDS; ++kt){
    if (tid < 64){
      uint32_t wb = g_xi[(t * NWORDS + kt) * B_SZ + bm0 + tid];
      #pragma unroll
      for (int kk = 0; kk < 32; ++kk)
        As[kk][tid] = ((wb >> kk) & 1u) ? 1.0f : 0.0f;
    }
    #pragma unroll
    for (int j = 0; j < 8; ++j){
      int idx = tid + j * 160;       // 0..1279 covers 40x32
      int n   = idx >> 5;
      int kk  = idx & 31;
      int kg  = kt * 32 + kk;
      Ws[kk][n] = (kg < IN_DIM) ? W1[(n0 + n) * IN_DIM + kg] : 0.0f;
    }
    __syncthreads();
    #pragma unroll
    for (int kk = 0; kk < 32; ++kk){
      float4 a = *(const float4*)&As[kk][tm * 4];
      float4 w = *(const float4*)&Ws[kk][tn * 4];
      c[0][0] += a.x*w.x; c[0][1] += a.x*w.y; c[0][2] += a.x*w.z; c[0][3] += a.x*w.w;
      c[1][0] += a.y*w.x; c[1][1] += a.y*w.y; c[1][2] += a.y*w.z; c[1][3] += a.y*w.w;
      c[2][0] += a.z*w.x; c[2][1] += a.z*w.y; c[2][2] += a.z*w.z; c[2][3] += a.z*w.w;
      c[3][0] += a.w*w.x; c[3][1] += a.w*w.y; c[3][2] += a.w*w.z; c[3][3] += a.w*w.w;
    }
    __syncthreads();
  }

  // LIF1: mem = mem*0.2*(1-spike_prev) + mm + b1  (spike recomputed from stored mem)
  float4 bb = *(const float4*)&b1[n0 + tn * 4];
  #pragma unroll
  for (int i = 0; i < 4; ++i){
    int m = bm0 + tm * 4 + i;
    float4* p = (float4*)&g_h1mem[m * HID + n0 + tn * 4];
    float4 old = *p;
    float4 nm;
    nm.x = ((old.x > 0.5f ? 0.0f : old.x * 0.2f) + c[i][0]) + bb.x;
    nm.y = ((old.y > 0.5f ? 0.0f : old.y * 0.2f) + c[i][1]) + bb.y;
    nm.z = ((old.z > 0.5f ? 0.0f : old.z * 0.2f) + c[i][2]) + bb.z;
    nm.w = ((old.w > 0.5f ? 0.0f : old.w * 0.2f) + c[i][3]) + bb.w;
    *p = nm;
  }
}

// -------- GEMM2 (h1_spike @ W2^T) fused with LIF layer 2 + output accumulation --------
// block: 64 rows, 4 threads/row (100 K each), W2 staged in smem
__global__ __launch_bounds__(256) void gemm2_lif(const float* __restrict__ W2,
                                                 const float* __restrict__ b2,
                                                 float* __restrict__ out, int t){
  __shared__ float W2s[HID][12];   // padded to 48B rows for vector LDS
  int tid = threadIdx.x;
  for (int idx = tid; idx < OUT_DIM * HID; idx += 256){
    int o = idx / HID, n = idx % HID;
    W2s[n][o] = W2[idx];
  }
  __syncthreads();

  int tr = tid >> 2, tq = tid & 3;
  int m  = blockIdx.x * 64 + tr;
  const float* hrow = &g_h1mem[m * HID + tq * 100];

  float acc[OUT_DIM] = {};
  #pragma unroll 5
  for (int j = 0; j < 100; j += 4){
    float4 h = *(const float4*)(hrow + j);
    int nb = tq * 100 + j;
    float s;
    s = (h.x > 0.5f) ? 1.0f : 0.0f;
    #pragma unroll
    for (int o = 0; o < OUT_DIM; ++o) acc[o] += s * W2s[nb + 0][o];
    s = (h.y > 0.5f) ? 1.0f : 0.0f;
    #pragma unroll
    for (int o = 0; o < OUT_DIM; ++o) acc[o] += s * W2s[nb + 1][o];
    s = (h.z > 0.5f) ? 1.0f : 0.0f;
    #pragma unroll
    for (int o = 0; o < OUT_DIM; ++o) acc[o] += s * W2s[nb + 2][o];
    s = (h.w > 0.5f) ? 1.0f : 0.0f;
    #pragma unroll
    for (int o = 0; o < OUT_DIM; ++o) acc[o] += s * W2s[nb + 3][o];
  }

  // reduce across the 4 threads of this row (adjacent lanes)
  #pragma unroll
  for (int o = 0; o < OUT_DIM; ++o){
    acc[o] += __shfl_xor_sync(0xffffffffu, acc[o], 1);
    acc[o] += __shfl_xor_sync(0xffffffffu, acc[o], 2);
  }

  if (tq == 0){
    #pragma unroll
    for (int o = 0; o < OUT_DIM; ++o){
      float old = g_h2mem[m * OUT_DIM + o];
      float nm  = ((old > 0.5f ? 0.0f : old * 0.2f) + acc[o]) + b2[o];
      g_h2mem[m * OUT_DIM + o] = nm;
      float s   = (nm > 0.5f) ? 1.0f : 0.0f;
      float sum = out[m * OUT_DIM + o] + s;
      out[m * OUT_DIM + o] = (t == T_STEPS - 1) ? (sum / (float)T_STEPS) : sum;
    }
  }
}

// -------- launch --------
extern "C" void kernel_launch(void* const* d_in, const int* in_sizes, int n_in,
                              void* d_out, int out_size){
  const float* x  = (const float*)d_in[0];
  const float* W1 = (const float*)d_in[1];
  const float* b1 = (const float*)d_in[2];
  const float* W2 = (const float*)d_in[3];
  const float* b2 = (const float*)d_in[4];
  float* out = (float*)d_out;

  // keys[t] = threefry((0,42), (0,t))   (split-foldlike, partitionable default)
  KeyArr keys;
  for (int t = 0; t < T_STEPS; ++t){
    unsigned o0, o1;
    threefry2x32(0u, 42u, 0u, (unsigned)t, o0, o1);
    keys.a[t] = o0; keys.b[t] = o1;
  }

  init_state<<<(B_SZ * HID + 255) / 256, 256>>>(out);

  dim3 gs(NWORDS, B_SZ / 8, T_STEPS);
  spikegen<<<gs, 256>>>(x, keys);

  for (int t = 0; t < T_STEPS; ++t){
    gemm1_lif<<<dim3(B_SZ / 64, HID / 40), 160>>>(W1, b1, t);
    gemm2_lif<<<B_SZ / 64, 256>>>(W2, b2, out, t);
  }
}

// round 2
// speedup vs baseline: 1.0002x; 1.0002x over previous
#include <cuda_runtime.h>
#include <cstdint>

#define B_SZ 16384
#define IN_DIM 784
#define HID 400
#define OUT_DIM 10
#define T_STEPS 20
#define NWORDS 25   // ceil(784/32), bits 784..799 padded to zero

// -------- scratch state (static device allocations; allowed) --------
__device__ uint32_t g_xi[T_STEPS * NWORDS * B_SZ];   // spike bitmasks [t][w][m]  (~33 MB)
__device__ float    g_h1mem[B_SZ * HID];             // LIF1 membrane (~26 MB)
__device__ float    g_h2mem[B_SZ * OUT_DIM];         // LIF2 membrane

struct KeyArr { unsigned int a[T_STEPS]; unsigned int b[T_STEPS]; };

// -------- threefry2x32 (exact JAX semantics, 20 rounds) --------
__host__ __device__ __forceinline__ void tf_round(unsigned &x0, unsigned &x1, int r){
  x0 += x1;
#ifdef __CUDA_ARCH__
  x1 = __funnelshift_l(x1, x1, r);   // rotate-left
#else
  x1 = (x1 << r) | (x1 >> (32 - r));
#endif
  x1 ^= x0;
}

__host__ __device__ __forceinline__ void threefry2x32(unsigned k0, unsigned k1,
                                                      unsigned x0, unsigned x1,
                                                      unsigned &o0, unsigned &o1){
  unsigned k2 = k0 ^ k1 ^ 0x1BD11BDAu;
  x0 += k0; x1 += k1;
  tf_round(x0,x1,13); tf_round(x0,x1,15); tf_round(x0,x1,26); tf_round(x0,x1, 6);
  x0 += k1; x1 += k2 + 1u;
  tf_round(x0,x1,17); tf_round(x0,x1,29); tf_round(x0,x1,16); tf_round(x0,x1,24);
  x0 += k2; x1 += k0 + 2u;
  tf_round(x0,x1,13); tf_round(x0,x1,15); tf_round(x0,x1,26); tf_round(x0,x1, 6);
  x0 += k0; x1 += k1 + 3u;
  tf_round(x0,x1,17); tf_round(x0,x1,29); tf_round(x0,x1,16); tf_round(x0,x1,24);
  x0 += k1; x1 += k2 + 4u;
  tf_round(x0,x1,13); tf_round(x0,x1,15); tf_round(x0,x1,26); tf_round(x0,x1, 6);
  x0 += k2; x1 += k0 + 5u;
  o0 = x0; o1 = x1;
}

// -------- init: zero all state + output accumulator --------
__global__ void init_state(float* __restrict__ out){
  int i = blockIdx.x * 256 + threadIdx.x;            // grid sized to exactly B*HID
  if (i < B_SZ * HID)   g_h1mem[i] = 0.0f;
  if (i < B_SZ * OUT_DIM){ g_h2mem[i] = 0.0f; out[i] = 0.0f; }
}

// -------- spike generation: all T steps, packed bitmasks --------
// partitionable threefry: bits(i) = o0^o1 of threefry(key_t, (0, i)), i = m*784+k
// u = bitcast((bits>>9)|0x3f800000) - 1 ; spike = x > u  (strict)
__global__ __launch_bounds__(256) void spikegen(const float* __restrict__ x, KeyArr keys){
  int w    = blockIdx.x;                       // word index 0..24
  int t    = blockIdx.z;                       // timestep
  int m    = blockIdx.y * 8 + (threadIdx.x >> 5);
  int lane = threadIdx.x & 31;
  int k    = w * 32 + lane;

  unsigned k1 = keys.a[t], k2 = keys.b[t];
  unsigned i  = (unsigned)m * IN_DIM + (unsigned)k;

  unsigned o0, o1;
  threefry2x32(k1, k2, 0u, i, o0, o1);
  unsigned bits = o0 ^ o1;
  float u = __uint_as_float((bits >> 9) | 0x3f800000u) - 1.0f;

  bool s = false;
  if (k < IN_DIM) s = (x[i] > u);
  unsigned word = __ballot_sync(0xffffffffu, s);
  if (lane == 0) g_xi[(t * NWORDS + w) * B_SZ + m] = word;
}

// -------- GEMM1 (xi @ W1^T) fused with LIF layer 1 --------
// block: 64 rows x 40 hidden cols, 160 threads, thread tile 4x4, BK=32 (one bit-word)
__global__ __launch_bounds__(160) void gemm1_lif(const float* __restrict__ W1,
                                                 const float* __restrict__ b1, int t){
  __shared__ float As[32][64];
  __shared__ float Ws[32][40];
  int tid = threadIdx.x;
  int bm0 = blockIdx.x * 64;
  int n0  = blockIdx.y * 40;
  int tn  = tid % 10;
  int tm  = tid / 10;   // 0..15
  float c[4][4] = {};

  for (int kt = 0; kt < NWORDS; ++kt){
    if (tid < 64){
      uint32_t wb = g_xi[(t * NWORDS + kt) * B_SZ + bm0 + tid];
      #pragma unroll
      for (int kk = 0; kk < 32; ++kk)
        As[kk][tid] = ((wb >> kk) & 1u) ? 1.0f : 0.0f;
    }
    #pragma unroll
    for (int j = 0; j < 8; ++j){
      int idx = tid + j * 160;       // 0..1279 covers 40x32
      int n   = idx >> 5;
      int kk  = idx & 31;
      int kg  = kt * 32 + kk;
      Ws[kk][n] = (kg < IN_DIM) ? W1[(n0 + n) * IN_DIM + kg] : 0.0f;
    }
    __syncthreads();
    #pragma unroll
    for (int kk = 0; kk < 32; ++kk){
      float4 a = *(const float4*)&As[kk][tm * 4];
      float4 w = *(const float4*)&Ws[kk][tn * 4];
      c[0][0] += a.x*w.x; c[0][1] += a.x*w.y; c[0][2] += a.x*w.z; c[0][3] += a.x*w.w;
      c[1][0] += a.y*w.x; c[1][1] += a.y*w.y; c[1][2] += a.y*w.z; c[1][3] += a.y*w.w;
      c[2][0] += a.z*w.x; c[2][1] += a.z*w.y; c[2][2] += a.z*w.z; c[2][3] += a.z*w.w;
      c[3][0] += a.w*w.x; c[3][1] += a.w*w.y; c[3][2] += a.w*w.z; c[3][3] += a.w*w.w;
    }
    __syncthreads();
  }

  // LIF1: mem = mem*0.2*(1-spike_prev) + mm + b1  (spike recomputed from stored mem)
  float4 bb = *(const float4*)&b1[n0 + tn * 4];
  #pragma unroll
  for (int i = 0; i < 4; ++i){
    int m = bm0 + tm * 4 + i;
    float4* p = (float4*)&g_h1mem[m * HID + n0 + tn * 4];
    float4 old = *p;
    float4 nm;
    nm.x = ((old.x > 0.5f ? 0.0f : old.x * 0.2f) + c[i][0]) + bb.x;
    nm.y = ((old.y > 0.5f ? 0.0f : old.y * 0.2f) + c[i][1]) + bb.y;
    nm.z = ((old.z > 0.5f ? 0.0f : old.z * 0.2f) + c[i][2]) + bb.z;
    nm.w = ((old.w > 0.5f ? 0.0f : old.w * 0.2f) + c[i][3]) + bb.w;
    *p = nm;
  }
}

// -------- GEMM2 (h1_spike @ W2^T) fused with LIF layer 2 + output accumulation --------
// block: 64 rows, 4 threads/row (100 K each), W2 staged in smem
__global__ __launch_bounds__(256) void gemm2_lif(const float* __restrict__ W2,
                                                 const float* __restrict__ b2,
                                                 float* __restrict__ out, int t){
  __shared__ float W2s[HID][12];   // padded to 48B rows for vector LDS
  int tid = threadIdx.x;
  for (int idx = tid; idx < OUT_DIM * HID; idx += 256){
    int o = idx / HID, n = idx % HID;
    W2s[n][o] = W2[idx];
  }
  __syncthreads();

  int tr = tid >> 2, tq = tid & 3;
  int m  = blockIdx.x * 64 + tr;
  const float* hrow = &g_h1mem[m * HID + tq * 100];

  float acc[OUT_DIM] = {};
  #pragma unroll 5
  for (int j = 0; j < 100; j += 4){
    float4 h = *(const float4*)(hrow + j);
    int nb = tq * 100 + j;
    float s;
    s = (h.x > 0.5f) ? 1.0f : 0.0f;
    #pragma unroll
    for (int o = 0; o < OUT_DIM; ++o) acc[o] += s * W2s[nb + 0][o];
    s = (h.y > 0.5f) ? 1.0f : 0.0f;
    #pragma unroll
    for (int o = 0; o < OUT_DIM; ++o) acc[o] += s * W2s[nb + 1][o];
    s = (h.z > 0.5f) ? 1.0f : 0.0f;
    #pragma unroll
    for (int o = 0; o < OUT_DIM; ++o) acc[o] += s * W2s[nb + 2][o];
    s = (h.w > 0.5f) ? 1.0f : 0.0f;
    #pragma unroll
    for (int o = 0; o < OUT_DIM; ++o) acc[o] += s * W2s[nb + 3][o];
  }

  // reduce across the 4 threads of this row (adjacent lanes)
  #pragma unroll
  for (int o = 0; o < OUT_DIM; ++o){
    acc[o] += __shfl_xor_sync(0xffffffffu, acc[o], 1);
    acc[o] += __shfl_xor_sync(0xffffffffu, acc[o], 2);
  }

  if (tq == 0){
    #pragma unroll
    for (int o = 0; o < OUT_DIM; ++o){
      float old = g_h2mem[m * OUT_DIM + o];
      float nm  = ((old > 0.5f ? 0.0f : old * 0.2f) + acc[o]) + b2[o];
      g_h2mem[m * OUT_DIM + o] = nm;
      float s   = (nm > 0.5f) ? 1.0f : 0.0f;
      float sum = out[m * OUT_DIM + o] + s;
      out[m * OUT_DIM + o] = (t == T_STEPS - 1) ? (sum / (float)T_STEPS) : sum;
    }
  }
}

// -------- launch --------
extern "C" void kernel_launch(void* const* d_in, const int* in_sizes, int n_in,
                              void* d_out, int out_size){
  const float* x  = (const float*)d_in[0];
  const float* W1 = (const float*)d_in[1];
  const float* b1 = (const float*)d_in[2];
  const float* W2 = (const float*)d_in[3];
  const float* b2 = (const float*)d_in[4];
  float* out = (float*)d_out;

  // keys[t] = threefry((0,42), (0,t))   (split-foldlike, partitionable default)
  KeyArr keys;
  for (int t = 0; t < T_STEPS; ++t){
    unsigned o0, o1;
    threefry2x32(0u, 42u, 0u, (unsigned)t, o0, o1);
    keys.a[t] = o0; keys.b[t] = o1;
  }

  init_state<<<(B_SZ * HID + 255) / 256, 256>>>(out);

  dim3 gs(NWORDS, B_SZ / 8, T_STEPS);
  spikegen<<<gs, 256>>>(x, keys);

  for (int t = 0; t < T_STEPS; ++t){
    gemm1_lif<<<dim3(B_SZ / 64, HID / 40), 160>>>(W1, b1, t);
    gemm2_lif<<<B_SZ / 64, 256>>>(W2, b2, out, t);
  }
}

// round 6
// speedup vs baseline: 1.2620x; 1.2618x over previous
#include <cuda_runtime.h>
#include <cstdint>

#define B_SZ 16384
#define IN_DIM 784
#define HID 400
#define T_STEPS 20
#define NB 10            // n-blocks of 40 columns
#define KC 25            // k-chunks of 32 (K padded 784->800)
#define BNB 96000u       // bytes per n-block, all 3 digits
#define B01SZ 64000u     // digits 0,1 packed region
#define OFF_B  0u        // 2 x 96000
#define OFF_AM 192000u   // 128 x 25 uint32 masks
#define OFF_F  204800u   // 400 x 12 floats (W2 cols + b1)
#define SMEM_REQ 224000

__device__ __align__(128) uint8_t g_wq[NB * BNB];  // quantized W1 digits
__device__ float g_c1[B_SZ * HID];                 // LIF1 carry [m][n]

struct KeyArr { unsigned a[T_STEPS], b[T_STEPS]; };

// ---------------- threefry2x32 (exact JAX semantics) ----------------
__host__ __device__ __forceinline__ void tfr(unsigned &x0, unsigned &x1, int r){
  x0 += x1;
#ifdef __CUDA_ARCH__
  x1 = __funnelshift_l(x1, x1, r);
#else
  x1 = (x1 << r) | (x1 >> (32 - r));
#endif
  x1 ^= x0;
}
__host__ __device__ __forceinline__ void tf2x32(unsigned k0, unsigned k1,
                                                unsigned x0, unsigned x1,
                                                unsigned &o0, unsigned &o1){
  unsigned k2 = k0 ^ k1 ^ 0x1BD11BDAu;
  x0 += k0; x1 += k1;
  tfr(x0,x1,13); tfr(x0,x1,15); tfr(x0,x1,26); tfr(x0,x1,6);  x0 += k1; x1 += k2 + 1u;
  tfr(x0,x1,17); tfr(x0,x1,29); tfr(x0,x1,16); tfr(x0,x1,24); x0 += k2; x1 += k0 + 2u;
  tfr(x0,x1,13); tfr(x0,x1,15); tfr(x0,x1,26); tfr(x0,x1,6);  x0 += k0; x1 += k1 + 3u;
  tfr(x0,x1,17); tfr(x0,x1,29); tfr(x0,x1,16); tfr(x0,x1,24); x0 += k1; x1 += k2 + 4u;
  tfr(x0,x1,13); tfr(x0,x1,15); tfr(x0,x1,26); tfr(x0,x1,6);  x0 += k2; x1 += k0 + 5u;
  o0 = x0; o1 = x1;
}
__device__ __forceinline__ float tf_u01(unsigned ka, unsigned kb, unsigned i){
  unsigned o0, o1; tf2x32(ka, kb, 0u, i, o0, o1);
  return __uint_as_float((((o0 ^ o1) >> 9) | 0x3f800000u)) - 1.0f;
}

// ---------------- prep: fp32 W1 -> 3 int8 digits (scale 2^24) ----------------
__global__ __launch_bounds__(256) void prep(const float* __restrict__ W1){
  int i = blockIdx.x * 256 + threadIdx.x;
  if (i >= HID * 800) return;
  int n = i / 800, k = i % 800;
  float w = (k < IN_DIM) ? W1[n * IN_DIM + k] : 0.0f;
  int v = __float2int_rn(w * 16777216.0f);          // w * 2^24
  int d0 = ((v & 0xFF) ^ 0x80) - 0x80;  v = (v - d0) >> 8;
  int d1 = ((v & 0xFF) ^ 0x80) - 0x80;  v = (v - d1) >> 8;
  int d2 = v;                                       // in [-128,127] given |w|<0.5
  int nb = n / 40, nn = n % 40;
  int kc = k >> 5, kk = k & 31;
  int half = kk >> 4, tig = (kk & 15) >> 2, j = kk & 3;
  unsigned grp = (unsigned)(nn * KC + kc) * 4u + (unsigned)tig;
  uint8_t* base = g_wq + (unsigned)nb * BNB;
  base[grp * 16u + 0u + half * 4u + j]  = (uint8_t)d0;   // d0: b0|b1
  base[grp * 16u + 8u + half * 4u + j]  = (uint8_t)d1;   // d1: b0|b1
  base[B01SZ + grp * 8u + half * 4u + j] = (uint8_t)d2;  // d2
}

// ---------------- device helpers ----------------
__device__ __forceinline__ uint32_t s2u(const void* p){
  uint32_t a; asm("{ .reg .u64 t; cvta.to.shared.u64 t, %1; cvt.u32.u64 %0, t; }" : "=r"(a) : "l"(p));
  return a;
}
__device__ __forceinline__ void imma(int* c, uint32_t a0, uint32_t a1, uint32_t a2,
                                     uint32_t a3, uint32_t b0, uint32_t b1){
  asm volatile("mma.sync.aligned.m16n8k32.row.col.s32.s8.s8.s32 "
               "{%0,%1,%2,%3}, {%4,%5,%6,%7}, {%8,%9}, {%0,%1,%2,%3};"
               : "+r"(c[0]), "+r"(c[1]), "+r"(c[2]), "+r"(c[3])
               : "r"(a0), "r"(a1), "r"(a2), "r"(a3), "r"(b0), "r"(b1));
}
__device__ __forceinline__ void cp_fill(uint8_t* dst, const uint8_t* src, int tid){
  uint32_t d = s2u(dst);
  for (unsigned ofs = (unsigned)tid * 16u; ofs < BNB; ofs += 4096u)
    asm volatile("cp.async.cg.shared.global [%0], [%1], 16;" :: "r"(d + ofs), "l"(src + ofs));
}
__device__ __forceinline__ uint32_t gen_word(const float* __restrict__ x,
                                             unsigned ka, unsigned kb, int cta, int w){
  int row = w / 25, wi = w - row * 25;
  unsigned i0 = (unsigned)(cta * 128 + row) * IN_DIM + (unsigned)(wi * 32);
  const float4* xp = (const float4*)(x + i0);
  int QQ = (wi == 24) ? 4 : 8;          // k 784..799 are zero padding
  uint32_t word = 0u;
  #pragma unroll 4
  for (int q = 0; q < QQ; q++){
    float4 xv = __ldg(xp + q);
    unsigned ib = i0 + (unsigned)(q * 4);
    word |= (xv.x > tf_u01(ka, kb, ib + 0u)) ? (1u << (q * 4 + 0)) : 0u;
    word |= (xv.y > tf_u01(ka, kb, ib + 1u)) ? (1u << (q * 4 + 1)) : 0u;
    word |= (xv.z > tf_u01(ka, kb, ib + 2u)) ? (1u << (q * 4 + 2)) : 0u;
    word |= (xv.w > tf_u01(ka, kb, ib + 3u)) ? (1u << (q * 4 + 3)) : 0u;
  }
  return word;
}

// ---------------- persistent SNN kernel ----------------
__global__ __launch_bounds__(256, 1) void snn(const float* __restrict__ x,
                                              const float* __restrict__ W2,
                                              const float* __restrict__ b1,
                                              const float* __restrict__ b2,
                                              float* __restrict__ out, KeyArr keys){
  extern __shared__ uint8_t SM[];
  float*    Ftab = (float*)(SM + OFF_F);
  uint32_t* AM   = (uint32_t*)(SM + OFF_AM);
  int tid = threadIdx.x, lane = tid & 31, wid = tid >> 5;
  int g = lane >> 2, tig = lane & 3, cta = blockIdx.x;
  int rA = wid * 16 + g, rB = rA + 8;          // local rows
  int mA = cta * 128 + rA, mB = cta * 128 + rB;
  int gbase = g * 100 + tig;

  for (int i = tid; i < HID * 12; i += 256){
    int n = i / 12, o = i % 12;
    Ftab[i] = (o < 10) ? W2[o * HID + n] : (o == 10 ? b1[n] : 0.0f);
  }
  float b2r[10];
  #pragma unroll
  for (int o = 0; o < 10; o++) b2r[o] = __ldg(b2 + o);
  float h2m[2][10] = {}, h2s[2][10] = {};

  // prefetch first weight block
  cp_fill(SM + OFF_B, g_wq, tid);
  asm volatile("cp.async.commit_group;" ::: "memory");

  for (int t = 0; t < T_STEPS; t++){
    // ---- spike mask generation for this timestep ----
    __syncthreads();                        // prior compute done reading AM
    unsigned ka = keys.a[t], kb = keys.b[t];
    #pragma unroll
    for (int j2 = 0; j2 < 13; j2++){
      int w = tid + (j2 << 8);
      if (w < 3200) AM[w] = gen_word(x, ka, kb, cta, w);
    }

    float acc10[2][10] = {};
    for (int nb = 0; nb < NB; nb++){
      int seq = t * NB + nb;
      __syncthreads();                      // buffer (seq+1)&1 free; AM visible
      if (seq + 1 < T_STEPS * NB){
        cp_fill(SM + OFF_B + (unsigned)((seq + 1) & 1) * BNB,
                g_wq + (unsigned)((nb + 1) % NB) * BNB, tid);
        asm volatile("cp.async.commit_group;" ::: "memory");
        asm volatile("cp.async.wait_group 1;" ::: "memory");
      } else {
        asm volatile("cp.async.wait_group 0;" ::: "memory");
      }
      __syncthreads();                      // buffer seq&1 fully loaded

      const uint8_t* Bb = SM + OFF_B + (unsigned)(seq & 1) * BNB;
      int accd[15][4] = {};

      #pragma unroll 5
      for (int kc = 0; kc < KC; kc++){
        uint32_t mAv = AM[rA * 25 + kc], mBv = AM[rB * 25 + kc];
        uint32_t sa = mAv >> (tig * 4), sb = mBv >> (tig * 4);
        uint32_t a0 = ((sa & 0xFu) * 0x204081u) & 0x01010101u;
        uint32_t a2 = (((sa >> 16) & 0xFu) * 0x204081u) & 0x01010101u;
        uint32_t a1 = ((sb & 0xFu) * 0x204081u) & 0x01010101u;
        uint32_t a3 = (((sb >> 16) & 0xFu) * 0x204081u) & 0x01010101u;
        #pragma unroll
        for (int n8 = 0; n8 < 5; n8++){
          unsigned grp = (unsigned)(n8 * 800 + kc * 4 + gbase);
          uint4 v01 = *(const uint4*)(Bb + grp * 16u);
          uint2 v2  = *(const uint2*)(Bb + B01SZ + grp * 8u);
          imma(accd[n8],      a0, a1, a2, a3, v01.x, v01.y);
          imma(accd[5 + n8],  a0, a1, a2, a3, v01.z, v01.w);
          imma(accd[10 + n8], a0, a1, a2, a3, v2.x,  v2.y);
        }
      }

      // ---- epilogue: digit combine (scale 2^-24) -> LIF1 -> GEMM2 partial ----
      #pragma unroll
      for (int n8 = 0; n8 < 5; n8++){
        #pragma unroll
        for (int j = 0; j < 2; j++){
          int n = nb * 40 + n8 * 8 + 2 * tig + j;
          const float4* Fp = (const float4*)(Ftab + n * 12);
          float4 F0 = Fp[0], F1 = Fp[1], F2 = Fp[2];   // w0..w9, b1=F2.z
          #pragma unroll
          for (int r = 0; r < 2; r++){
            int ri = r * 2 + j;
            float f = fmaf(__int2float_rn(accd[10 + n8][ri]), 0.00390625f,
                      fmaf(__int2float_rn(accd[5 + n8][ri]), 1.52587890625e-05f,
                           __int2float_rn(accd[n8][ri]) * 5.9604644775390625e-08f));
            int m = r ? mB : mA;
            float* cp_ = g_c1 + (size_t)m * HID + n;
            float carry = t ? *cp_ : 0.0f;
            float mem = (carry + f) + F2.z;
            bool s = mem > 0.5f;
            *cp_ = s ? 0.0f : 0.2f * mem;
            if (s){
              acc10[r][0] += F0.x; acc10[r][1] += F0.y; acc10[r][2] += F0.z; acc10[r][3] += F0.w;
              acc10[r][4] += F1.x; acc10[r][5] += F1.y; acc10[r][6] += F1.z; acc10[r][7] += F1.w;
              acc10[r][8] += F2.x; acc10[r][9] += F2.y;
            }
          }
        }
      }
    }

    // ---- LIF2 + output accumulation (per-row, reduced over the 4 tig lanes) ----
    #pragma unroll
    for (int r = 0; r < 2; r++){
      #pragma unroll
      for (int o = 0; o < 10; o++){
        float v = acc10[r][o];
        v += __shfl_xor_sync(0xffffffffu, v, 1);
        v += __shfl_xor_sync(0xffffffffu, v, 2);
        float m2 = (h2m[r][o] + v) + b2r[o];
        bool s2 = m2 > 0.5f;
        h2m[r][o] = s2 ? 0.0f : 0.2f * m2;
        h2s[r][o] += s2 ? 1.0f : 0.0f;
      }
    }
  }

  if (tig == 0){
    #pragma unroll
    for (int o = 0; o < 10; o++){
      out[mA * 10 + o] = h2s[0][o] * 0.05f;
      out[mB * 10 + o] = h2s[1][o] * 0.05f;
    }
  }
}

// ---------------- launch ----------------
extern "C" void kernel_launch(void* const* d_in, const int* in_sizes, int n_in,
                              void* d_out, int out_size){
  const float* x  = (const float*)d_in[0];
  const float* W1 = (const float*)d_in[1];
  const float* b1 = (const float*)d_in[2];
  const float* W2 = (const float*)d_in[3];
  const float* b2 = (const float*)d_in[4];
  float* out = (float*)d_out;

  KeyArr keys;
  for (int t = 0; t < T_STEPS; t++){
    unsigned o0, o1;
    tf2x32(0u, 42u, 0u, (unsigned)t, o0, o1);
    keys.a[t] = o0; keys.b[t] = o1;
  }

  cudaFuncSetAttribute(snn, cudaFuncAttributeMaxDynamicSharedMemorySize, SMEM_REQ);
  prep<<<(HID * 800 + 255) / 256, 256>>>(W1);
  snn<<<128, 256, SMEM_REQ>>>(x, W2, b1, b2, out, keys);
}

// round 7
// speedup vs baseline: 1.5700x; 1.2440x over previous
#include <cuda_runtime.h>
#include <cstdint>

#define B_SZ 16384
#define IN_DIM 784
#define HID 400
#define T_STEPS 20
#define NB 25             // n-blocks of 16 columns
#define KC 25             // k-chunks of 32 (K padded 784->800)
#define BNB 38400u        // bytes per n-block (all 3 digits)
#define B01SZ 25600u      // digits 0,1 region within a block
#define OFF_B   0u        // 2 x 38400
#define OFF_AM  76800u    // 2 x 12800 (mask double buffer)
#define OFF_F   102400u   // 400 x 12 floats
#define OFF_H2M 121600u   // 128 x 10 floats
#define OFF_H2S 126720u   // 128 x 10 floats
#define OFF_B2  131840u   // 10 floats
#define SMEM_REQ 132000

__device__ __align__(128) uint8_t g_wq[NB * BNB];  // quantized W1 digits
__device__ float g_c1[HID * B_SZ];                 // LIF1 carry, transposed [n][m]

struct KeyArr { unsigned a[T_STEPS], b[T_STEPS]; };

// ---------------- threefry2x32 (exact JAX semantics) ----------------
__host__ __device__ __forceinline__ void tfr(unsigned &x0, unsigned &x1, int r){
  x0 += x1;
#ifdef __CUDA_ARCH__
  x1 = __funnelshift_l(x1, x1, r);
#else
  x1 = (x1 << r) | (x1 >> (32 - r));
#endif
  x1 ^= x0;
}
__host__ __device__ __forceinline__ void tf2x32(unsigned k0, unsigned k1,
                                                unsigned x0, unsigned x1,
                                                unsigned &o0, unsigned &o1){
  unsigned k2 = k0 ^ k1 ^ 0x1BD11BDAu;
  x0 += k0; x1 += k1;
  tfr(x0,x1,13); tfr(x0,x1,15); tfr(x0,x1,26); tfr(x0,x1,6);  x0 += k1; x1 += k2 + 1u;
  tfr(x0,x1,17); tfr(x0,x1,29); tfr(x0,x1,16); tfr(x0,x1,24); x0 += k2; x1 += k0 + 2u;
  tfr(x0,x1,13); tfr(x0,x1,15); tfr(x0,x1,26); tfr(x0,x1,6);  x0 += k0; x1 += k1 + 3u;
  tfr(x0,x1,17); tfr(x0,x1,29); tfr(x0,x1,16); tfr(x0,x1,24); x0 += k1; x1 += k2 + 4u;
  tfr(x0,x1,13); tfr(x0,x1,15); tfr(x0,x1,26); tfr(x0,x1,6);  x0 += k2; x1 += k0 + 5u;
  o0 = x0; o1 = x1;
}
__device__ __forceinline__ float tf_u01(unsigned ka, unsigned kb, unsigned i){
  unsigned o0, o1; tf2x32(ka, kb, 0u, i, o0, o1);
  return __uint_as_float((((o0 ^ o1) >> 9) | 0x3f800000u)) - 1.0f;
}

// ---------------- prep: fp32 W1 -> 3 int8 digits (scale 2^24) ----------------
__global__ __launch_bounds__(256) void prep(const float* __restrict__ W1){
  int i = blockIdx.x * 256 + threadIdx.x;
  if (i >= HID * 800) return;
  int n = i / 800, k = i % 800;
  float w = (k < IN_DIM) ? W1[n * IN_DIM + k] : 0.0f;
  int v = __float2int_rn(w * 16777216.0f);          // w * 2^24
  int d0 = ((v & 0xFF) ^ 0x80) - 0x80;  v = (v - d0) >> 8;
  int d1 = ((v & 0xFF) ^ 0x80) - 0x80;  v = (v - d1) >> 8;
  int d2 = v;
  int nb = n / 16, nn = n % 16;
  int kc = k >> 5, kk = k & 31;
  int half = kk >> 4, tig = (kk & 15) >> 2, j = kk & 3;
  unsigned grp = (unsigned)(nn * KC + kc) * 4u + (unsigned)tig;
  uint8_t* base = g_wq + (unsigned)nb * BNB;
  base[grp * 16u + 0u + half * 4u + j]   = (uint8_t)d0;
  base[grp * 16u + 8u + half * 4u + j]   = (uint8_t)d1;
  base[B01SZ + grp * 8u + half * 4u + j] = (uint8_t)d2;
}

// ---------------- device helpers ----------------
__device__ __forceinline__ uint32_t s2u(const void* p){
  uint32_t a; asm("{ .reg .u64 t; cvta.to.shared.u64 t, %1; cvt.u32.u64 %0, t; }" : "=r"(a) : "l"(p));
  return a;
}
__device__ __forceinline__ void imma(int* c, uint32_t a0, uint32_t a1, uint32_t a2,
                                     uint32_t a3, uint32_t b0, uint32_t b1){
  asm volatile("mma.sync.aligned.m16n8k32.row.col.s32.s8.s8.s32 "
               "{%0,%1,%2,%3}, {%4,%5,%6,%7}, {%8,%9}, {%0,%1,%2,%3};"
               : "+r"(c[0]), "+r"(c[1]), "+r"(c[2]), "+r"(c[3])
               : "r"(a0), "r"(a1), "r"(a2), "r"(a3), "r"(b0), "r"(b1));
}
__device__ __forceinline__ void cp_fill(uint8_t* dst, const uint8_t* src, int ctid){
  uint32_t d = s2u(dst);
  for (unsigned ofs = (unsigned)ctid * 16u; ofs < BNB; ofs += 4096u)
    asm volatile("cp.async.cg.shared.global [%0], [%1], 16;" :: "r"(d + ofs), "l"(src + ofs));
}
__device__ __forceinline__ void bar_cons(){          // consumer-only barrier (256 threads)
  asm volatile("bar.sync 1, 256;" ::: "memory");
}
__device__ __forceinline__ uint32_t gen_word(const float* __restrict__ x,
                                             unsigned ka, unsigned kb, int cta, int w){
  int row = w / 25, wi = w - row * 25;
  unsigned i0 = (unsigned)(cta * 128 + row) * IN_DIM + (unsigned)(wi * 32);
  const float4* xp = (const float4*)(x + i0);
  int QQ = (wi == 24) ? 4 : 8;
  uint32_t word = 0u;
  #pragma unroll 4
  for (int q = 0; q < QQ; q++){
    float4 xv = __ldg(xp + q);
    unsigned ib = i0 + (unsigned)(q * 4);
    word |= (xv.x > tf_u01(ka, kb, ib + 0u)) ? (1u << (q * 4 + 0)) : 0u;
    word |= (xv.y > tf_u01(ka, kb, ib + 1u)) ? (1u << (q * 4 + 1)) : 0u;
    word |= (xv.z > tf_u01(ka, kb, ib + 2u)) ? (1u << (q * 4 + 2)) : 0u;
    word |= (xv.w > tf_u01(ka, kb, ib + 3u)) ? (1u << (q * 4 + 3)) : 0u;
  }
  return word;
}

// ---------------- persistent warp-specialized SNN kernel ----------------
__global__ __launch_bounds__(512, 1) void snn(const float* __restrict__ x,
                                              const float* __restrict__ W2,
                                              const float* __restrict__ b1,
                                              const float* __restrict__ b2,
                                              float* __restrict__ out, KeyArr keys){
  extern __shared__ uint8_t SM[];
  float* Ftab = (float*)(SM + OFF_F);
  float* Sh2m = (float*)(SM + OFF_H2M);
  float* Sh2s = (float*)(SM + OFF_H2S);
  float* Sb2  = (float*)(SM + OFF_B2);
  int tid = threadIdx.x, lane = tid & 31, wid = tid >> 5, cta = blockIdx.x;
  int g = lane >> 2, tig = lane & 3;

  // smem tables (all threads)
  for (int i = tid; i < HID * 12; i += 512){
    int n = i / 12, o = i % 12;
    Ftab[i] = (o < 10) ? W2[o * HID + n] : (o == 10 ? b1[n] : 0.0f);
  }
  for (int i = tid; i < 1280; i += 512){ Sh2m[i] = 0.0f; Sh2s[i] = 0.0f; }
  if (tid < 10) Sb2[tid] = b2[tid];

  if (wid >= 8){
    // producers: generate masks for t=0
    int ptid = tid - 256;
    unsigned ka = keys.a[0], kb = keys.b[0];
    uint32_t* AMd = (uint32_t*)(SM + OFF_AM);
    #pragma unroll
    for (int j = 0; j < 13; j++){
      int w = ptid + (j << 8);
      if (w < 3200) AMd[w] = gen_word(x, ka, kb, cta, w);
    }
  } else {
    // consumers: prefetch first weight block
    cp_fill(SM + OFF_B, g_wq, tid);
    asm volatile("cp.async.commit_group;" ::: "memory");
  }
  __syncthreads();

  int rA = wid * 16 + g, rB = rA + 8;     // consumer rows (valid for wid<8)
  int mA = cta * 128 + rA, mB = mA + 8;
  int gbase = g * 100 + tig;

  for (int t = 0; t < T_STEPS; t++){
    if (wid < 8){
      // ================= consumers =================
      const uint32_t* AMt = (const uint32_t*)(SM + OFF_AM + (unsigned)(t & 1) * 12800u);
      float acc10[2][10] = {};

      for (int nb = 0; nb < NB; nb++){
        int seq = t * NB + nb;
        bar_cons();                       // buffer (seq+1)&1 free
        if (seq + 1 < T_STEPS * NB){
          cp_fill(SM + OFF_B + (unsigned)((seq + 1) & 1) * BNB,
                  g_wq + (unsigned)((nb + 1) % NB) * BNB, tid);
          asm volatile("cp.async.commit_group;" ::: "memory");
          asm volatile("cp.async.wait_group 1;" ::: "memory");
        } else {
          asm volatile("cp.async.wait_group 0;" ::: "memory");
        }
        bar_cons();                       // buffer seq&1 loaded

        const uint8_t* Bb = SM + OFF_B + (unsigned)(seq & 1) * BNB;
        int accd[6][4] = {};

        #pragma unroll 5
        for (int kc = 0; kc < KC; kc++){
          uint32_t mAv = AMt[rA * 25 + kc], mBv = AMt[rB * 25 + kc];
          uint32_t sa = mAv >> (tig * 4), sb = mBv >> (tig * 4);
          uint32_t a0 = ((sa & 0xFu) * 0x204081u) & 0x01010101u;
          uint32_t a2 = (((sa >> 16) & 0xFu) * 0x204081u) & 0x01010101u;
          uint32_t a1 = ((sb & 0xFu) * 0x204081u) & 0x01010101u;
          uint32_t a3 = (((sb >> 16) & 0xFu) * 0x204081u) & 0x01010101u;
          #pragma unroll
          for (int n8 = 0; n8 < 2; n8++){
            unsigned grp = (unsigned)(n8 * 800 + kc * 4 + gbase);
            uint4 v01 = *(const uint4*)(Bb + grp * 16u);
            uint2 v2  = *(const uint2*)(Bb + B01SZ + grp * 8u);
            imma(accd[n8],     a0, a1, a2, a3, v01.x, v01.y);   // d0
            imma(accd[2 + n8], a0, a1, a2, a3, v01.z, v01.w);   // d1
            imma(accd[4 + n8], a0, a1, a2, a3, v2.x,  v2.y);    // d2
          }
        }

        // epilogue: combine digits -> LIF1 -> GEMM2 partial
        #pragma unroll
        for (int n8 = 0; n8 < 2; n8++){
          #pragma unroll
          for (int j = 0; j < 2; j++){
            int n = nb * 16 + n8 * 8 + 2 * tig + j;
            const float4* Fp = (const float4*)(Ftab + n * 12);
            float4 F0 = Fp[0], F1 = Fp[1], F2 = Fp[2];   // w0..w9, b1 = F2.z
            #pragma unroll
            for (int r = 0; r < 2; r++){
              int ri = r * 2 + j;
              float f = fmaf(__int2float_rn(accd[4 + n8][ri]), 0.00390625f,
                        fmaf(__int2float_rn(accd[2 + n8][ri]), 1.52587890625e-05f,
                             __int2float_rn(accd[n8][ri]) * 5.9604644775390625e-08f));
              int m = r ? mB : mA;
              float* cp_ = g_c1 + (size_t)n * B_SZ + m;     // transposed, coalesced
              float carry = t ? *cp_ : 0.0f;
              float mem = (carry + f) + F2.z;
              bool s = mem > 0.5f;
              *cp_ = s ? 0.0f : 0.2f * mem;
              if (s){
                acc10[r][0] += F0.x; acc10[r][1] += F0.y; acc10[r][2] += F0.z; acc10[r][3] += F0.w;
                acc10[r][4] += F1.x; acc10[r][5] += F1.y; acc10[r][6] += F1.z; acc10[r][7] += F1.w;
                acc10[r][8] += F2.x; acc10[r][9] += F2.y;
              }
            }
          }
        }
      }

      // LIF2 + spike-sum update (per row; reduce over 4 tig lanes)
      #pragma unroll
      for (int r = 0; r < 2; r++){
        int rl = r ? rB : rA;
        #pragma unroll
        for (int o = 0; o < 10; o++){
          float v = acc10[r][o];
          v += __shfl_xor_sync(0xffffffffu, v, 1);
          v += __shfl_xor_sync(0xffffffffu, v, 2);
          if (tig == 0){
            float m2 = (Sh2m[rl * 10 + o] + v) + Sb2[o];
            bool s2 = m2 > 0.5f;
            Sh2m[rl * 10 + o] = s2 ? 0.0f : 0.2f * m2;
            Sh2s[rl * 10 + o] += s2 ? 1.0f : 0.0f;
          }
        }
      }
    } else {
      // ================= producers: masks for t+1 =================
      if (t + 1 < T_STEPS){
        int ptid = tid - 256;
        unsigned ka = keys.a[t + 1], kb = keys.b[t + 1];
        uint32_t* AMd = (uint32_t*)(SM + OFF_AM + (unsigned)((t + 1) & 1) * 12800u);
        #pragma unroll
        for (int j = 0; j < 13; j++){
          int w = ptid + (j << 8);
          if (w < 3200) AMd[w] = gen_word(x, ka, kb, cta, w);
        }
      }
    }
    __syncthreads();
  }

  // output
  for (int i = tid; i < 1280; i += 512){
    int m = i / 10, o = i % 10;
    out[(cta * 128 + m) * 10 + o] = Sh2s[m * 10 + o] * 0.05f;
  }
}

// ---------------- launch ----------------
extern "C" void kernel_launch(void* const* d_in, const int* in_sizes, int n_in,
                              void* d_out, int out_size){
  const float* x  = (const float*)d_in[0];
  const float* W1 = (const float*)d_in[1];
  const float* b1 = (const float*)d_in[2];
  const float* W2 = (const float*)d_in[3];
  const float* b2 = (const float*)d_in[4];
  float* out = (float*)d_out;

  KeyArr keys;
  for (int t = 0; t < T_STEPS; t++){
    unsigned o0, o1;
    tf2x32(0u, 42u, 0u, (unsigned)t, o0, o1);
    keys.a[t] = o0; keys.b[t] = o1;
  }

  cudaFuncSetAttribute(snn, cudaFuncAttributeMaxDynamicSharedMemorySize, SMEM_REQ);
  prep<<<(HID * 800 + 255) / 256, 256>>>(W1);
  snn<<<128, 512, SMEM_REQ>>>(x, W2, b1, b2, out, keys);
}